// round 6
// baseline (speedup 1.0000x reference)
#include <cuda_runtime.h>
#include <cuda_bf16.h>
#include <math.h>
#include <float.h>

// ---------------------------------------------------------------------------
// Problem constants
// ---------------------------------------------------------------------------
#define BATCH 16
#define CIN   512
#define OC    512
#define HWPIX 4096                 // 64*64
#define NPIX  (BATCH*HWPIX)        // 65536
#define NA    9
#define NANCH (HWPIX*NA)           // 36864 per image
#define PRE_NMS 6000
#define POST_NMS 300
#define NEGF (-1e30f)

// Output layout: reg [B,36864,4] | cls [B,36864,2] | rois [B,300,5]
#define CLS_OFF  (BATCH*NANCH*4)
#define ROIS_OFF (CLS_OFF + BATCH*NANCH*2)

// ---------------------------------------------------------------------------
// Device scratch
// ---------------------------------------------------------------------------
__device__ float g_wt[9*CIN*OC];            // [tap][ic][oc]
__device__ float g_wk[CIN*54];              // [ic][o] o<18 cls, else reg
__device__ float g_shared[(size_t)NPIX*OC]; // NHWC shared features
__device__ float g_boxes[BATCH*NANCH*4];
__device__ float g_scores[BATCH*NANCH];
__device__ float  g_cand_s[BATCH*PRE_NMS];
__device__ float4 g_cand_b[BATCH*PRE_NMS];
__device__ float g_abase[NA*4];

// ---------------------------------------------------------------------------
// k0a: W_share [oc][ic][3][3] -> g_wt [tap][ic][oc]
// ---------------------------------------------------------------------------
__global__ void k_wt_transform(const float* __restrict__ Wsh) {
    int idx = blockIdx.x * blockDim.x + threadIdx.x;
    if (idx >= OC * CIN * 9) return;
    int oc = idx / (CIN * 9);
    int rem = idx - oc * (CIN * 9);
    int ic = rem / 9;
    int t  = rem - ic * 9;
    g_wt[((size_t)t * CIN + ic) * OC + oc] = Wsh[idx];
}

// ---------------------------------------------------------------------------
// k0b: head weights [ic][54] and anchor base (double math, cast f32)
// ---------------------------------------------------------------------------
__global__ void k_wk_build(const float* __restrict__ Wcls, const float* __restrict__ Wreg) {
    int idx = blockIdx.x * blockDim.x + threadIdx.x;
    if (idx < CIN * 54) {
        int ic = idx / 54;
        int o  = idx - ic * 54;
        g_wk[idx] = (o < 18) ? Wcls[o * CIN + ic] : Wreg[(o - 18) * CIN + ic];
    }
    if (blockIdx.x == 0 && threadIdx.x < NA) {
        int a = threadIdx.x;
        const double ratios[3] = {0.5, 1.0, 2.0};
        const double scales[3] = {8.0, 16.0, 32.0};
        int r = a / 3, s = a % 3;
        double hh = (16.0 * scales[s]) * sqrt(ratios[r]);
        double ww = (16.0 * scales[s]) * sqrt(1.0 / ratios[r]);
        g_abase[a*4+0] = (float)(8.0 - ww/2.0);
        g_abase[a*4+1] = (float)(8.0 - hh/2.0);
        g_abase[a*4+2] = (float)(8.0 + ww/2.0);
        g_abase[a*4+3] = (float)(8.0 + hh/2.0);
    }
}

// ---------------------------------------------------------------------------
// k1: 3x3 conv + bias + relu.
//     ACCUMULATION HYPOTHESIS (this round): per-tap partial sums.
//       out = ((p0 + p1) + p2) + ... + p8,   tap order t = ky*3+kx ascending,
//       p_t = serial FMA chain over ic = 0..511 ascending (fresh accumulator).
//     This reproduces a "9 shifted GEMMs with beta=1" / tap-major implicit
//     GEMM rounding pattern. Tile: 128 px x 128 oc, 256 thr, 8x8 micro.
// ---------------------------------------------------------------------------
#define BKK 16
__global__ __launch_bounds__(256, 1) void k_conv3x3(const float* __restrict__ x,
                                                    const float* __restrict__ bsh) {
    const int nb = blockIdx.x;          // 0..3 (oc block of 128)
    const int mb = blockIdx.y;          // 0..511
    const int b  = mb >> 5;
    const int h0 = (mb & 31) * 2;
    const int tid = threadIdx.x;
    const int tx = tid & 15, ty = tid >> 4;

    __shared__ float As[BKK][128+4];
    __shared__ float Bs[BKK][128+4];

    float tot[8][8];
    float pt[8][8];
    #pragma unroll
    for (int r = 0; r < 8; ++r)
        #pragma unroll
        for (int c = 0; c < 8; ++c) tot[r][c] = 0.f;

    const float* xb = x + (size_t)b * CIN * HWPIX;

    for (int t = 0; t < 9; ++t) {
        const int ky = t / 3 - 1;
        const int kx = t % 3 - 1;
        const float* wt = g_wt + (size_t)t * CIN * OC;

        #pragma unroll
        for (int r = 0; r < 8; ++r)
            #pragma unroll
            for (int c = 0; c < 8; ++c) pt[r][c] = 0.f;

        for (int ic0 = 0; ic0 < CIN; ic0 += BKK) {
            // A tile: As[kk][p] = x[b][ic0+kk][h0 + p/64 + ky][p%64 + kx]
            #pragma unroll
            for (int i = 0; i < 8; ++i) {
                int e = i * 256 + tid;
                int kk = e >> 7, p = e & 127;
                int h = h0 + (p >> 6) + ky;
                int w = (p & 63) + kx;
                float v = 0.f;
                if ((unsigned)h < 64u && (unsigned)w < 64u)
                    v = xb[((size_t)(ic0 + kk)) * HWPIX + h * 64 + w];
                As[kk][p] = v;
            }
            // B tile: Bs[kk][oc] = g_wt[t][ic0+kk][nb*128+oc]
            #pragma unroll
            for (int i = 0; i < 8; ++i) {
                int e = i * 256 + tid;
                int kk = e >> 7, oc = e & 127;
                Bs[kk][oc] = wt[(size_t)(ic0 + kk) * OC + nb * 128 + oc];
            }
            __syncthreads();
            #pragma unroll
            for (int kk = 0; kk < BKK; ++kk) {
                float a[8], bb[8];
                #pragma unroll
                for (int r = 0; r < 8; ++r) a[r] = As[kk][ty * 8 + r];
                #pragma unroll
                for (int c = 0; c < 8; ++c) bb[c] = Bs[kk][tx * 8 + c];
                #pragma unroll
                for (int r = 0; r < 8; ++r)
                    #pragma unroll
                    for (int c = 0; c < 8; ++c)
                        pt[r][c] = fmaf(a[r], bb[c], pt[r][c]);
            }
            __syncthreads();
        }

        // sequential tap combine: tot = tot + p_t  (single rounded add per tap)
        #pragma unroll
        for (int r = 0; r < 8; ++r)
            #pragma unroll
            for (int c = 0; c < 8; ++c)
                tot[r][c] = __fadd_rn(tot[r][c], pt[r][c]);
    }

    // epilogue: bias + relu -> NHWC
    #pragma unroll
    for (int r = 0; r < 8; ++r) {
        int p = ty * 8 + r;
        size_t rowbase = ((size_t)b * HWPIX + h0 * 64 + p) * OC + nb * 128 + tx * 8;
        #pragma unroll
        for (int c = 0; c < 8; ++c) {
            float v = __fadd_rn(tot[r][c], bsh[nb * 128 + tx * 8 + c]);
            g_shared[rowbase + c] = fmaxf(v, 0.f);
        }
    }
}

// ---------------------------------------------------------------------------
// k2: 1x1 heads (serial ascending over ic) + softmax + decode/clip/min-size.
//     Elementwise math via _rn intrinsics (no FMA contraction), expf libdevice.
// ---------------------------------------------------------------------------
__global__ __launch_bounds__(256) void k_heads(const float* __restrict__ bcls,
                                               const float* __restrict__ breg,
                                               float* __restrict__ out) {
    __shared__ float xs[256][33];
    __shared__ float ws[32][54];
    const int tid = threadIdx.x;
    const int pixBase = blockIdx.x * 256;
    const int pix = pixBase + tid;
    const int warp = tid >> 5, lane = tid & 31;

    float acc[54];
    #pragma unroll
    for (int o = 0; o < 54; ++o) acc[o] = 0.f;

    for (int ic0 = 0; ic0 < CIN; ic0 += 32) {
        #pragma unroll 4
        for (int i = 0; i < 32; ++i) {
            int px = warp * 32 + i;
            xs[px][lane] = g_shared[(size_t)(pixBase + px) * OC + ic0 + lane];
        }
        for (int j = tid; j < 32 * 54; j += 256)
            ws[j / 54][j % 54] = g_wk[(ic0 + j / 54) * 54 + j % 54];
        __syncthreads();
        #pragma unroll
        for (int ic = 0; ic < 32; ++ic) {
            float v = xs[tid][ic];
            #pragma unroll
            for (int o = 0; o < 54; ++o)
                acc[o] = fmaf(v, ws[ic][o], acc[o]);
        }
        __syncthreads();
    }

    const int b  = pix >> 12;
    const int pi = pix & 4095;
    const int h  = pi >> 6, w = pi & 63;

    #pragma unroll
    for (int o = 0; o < 18; ++o) acc[o] = __fadd_rn(acc[o], bcls[o]);
    #pragma unroll
    for (int o = 18; o < 54; ++o) acc[o] = __fadd_rn(acc[o], breg[o - 18]);

    const float shx = (float)(w * 16);
    const float shy = (float)(h * 16);

    #pragma unroll
    for (int a = 0; a < NA; ++a) {
        float l0 = acc[2 * a], l1 = acc[2 * a + 1];
        float m = fmaxf(l0, l1);
        float e0 = expf(__fsub_rn(l0, m)), e1 = expf(__fsub_rn(l1, m));
        float s = __fadd_rn(e0, e1);
        float p0 = __fdiv_rn(e0, s), p1 = __fdiv_rn(e1, s);

        size_t n = (size_t)b * NANCH + (size_t)pi * NA + a;
        out[CLS_OFF + n * 2]     = p0;
        out[CLS_OFF + n * 2 + 1] = p1;

        float dxv = acc[18 + a * 4 + 0];
        float dyv = acc[18 + a * 4 + 1];
        float dwv = acc[18 + a * 4 + 2];
        float dhv = acc[18 + a * 4 + 3];
        out[n * 4 + 0] = dxv;
        out[n * 4 + 1] = dyv;
        out[n * 4 + 2] = dwv;
        out[n * 4 + 3] = dhv;

        float ax1 = __fadd_rn(shx, g_abase[a * 4 + 0]);
        float ay1 = __fadd_rn(shy, g_abase[a * 4 + 1]);
        float ax2 = __fadd_rn(shx, g_abase[a * 4 + 2]);
        float ay2 = __fadd_rn(shy, g_abase[a * 4 + 3]);
        float aw = __fsub_rn(ax2, ax1);
        float ah = __fsub_rn(ay2, ay1);
        float actx = __fadd_rn(ax1, __fmul_rn(0.5f, aw));
        float acty = __fadd_rn(ay1, __fmul_rn(0.5f, ah));
        float cx = __fadd_rn(__fmul_rn(dxv, aw), actx);
        float cy = __fadd_rn(__fmul_rn(dyv, ah), acty);
        float bw = __fmul_rn(expf(dwv), aw);
        float bh = __fmul_rn(expf(dhv), ah);
        float x1 = __fsub_rn(cx, __fmul_rn(0.5f, bw));
        float y1 = __fsub_rn(cy, __fmul_rn(0.5f, bh));
        float x2 = __fadd_rn(cx, __fmul_rn(0.5f, bw));
        float y2 = __fadd_rn(cy, __fmul_rn(0.5f, bh));
        x1 = fminf(fmaxf(x1, 0.f), 1024.f);
        y1 = fminf(fmaxf(y1, 0.f), 1024.f);
        x2 = fminf(fmaxf(x2, 0.f), 1024.f);
        y2 = fminf(fmaxf(y2, 0.f), 1024.f);
        float wsz = __fsub_rn(x2, x1), hsz = __fsub_rn(y2, y1);
        float sc = (wsz >= 16.f && hsz >= 16.f) ? p1 : NEGF;

        g_boxes[n * 4 + 0] = x1;
        g_boxes[n * 4 + 1] = y1;
        g_boxes[n * 4 + 2] = x2;
        g_boxes[n * 4 + 3] = y2;
        g_scores[n] = sc;
    }
}

// ---------------------------------------------------------------------------
// k3: per-image exact top-6000 set, stable (index-ordered) compaction
// ---------------------------------------------------------------------------
__device__ __forceinline__ unsigned score_key(float f) {
    unsigned u = __float_as_uint(f);
    return (u & 0x80000000u) ? ~u : (u | 0x80000000u);
}

__global__ __launch_bounds__(1024) void k_select() {
    const int b = blockIdx.x;
    const int tid = threadIdx.x;
    const int warp = tid >> 5, lane = tid & 31;
    const float* sc = g_scores + (size_t)b * NANCH;
    __shared__ unsigned hist[256];
    __shared__ unsigned sel_prefix;
    __shared__ int sel_needed;
    __shared__ int warpG[32], warpE[32];
    __shared__ int base_g, base_e;

    unsigned prefix = 0, maskHi = 0;
    int needed = PRE_NMS;

    for (int shift = 24; shift >= 0; shift -= 8) {
        for (int i = tid; i < 256; i += 1024) hist[i] = 0;
        __syncthreads();
        for (int j = tid; j < NANCH; j += 1024) {
            unsigned u = score_key(sc[j]);
            if ((u & maskHi) == prefix)
                atomicAdd(&hist[(u >> shift) & 255u], 1u);
        }
        __syncthreads();
        if (tid == 0) {
            int need = needed;
            int bsel = 0;
            for (int bin = 255; bin >= 0; --bin) {
                int c = (int)hist[bin];
                if (c >= need) { bsel = bin; break; }
                need -= c;
            }
            sel_needed = need;
            sel_prefix = prefix | ((unsigned)bsel << shift);
        }
        __syncthreads();
        needed = sel_needed;
        prefix = sel_prefix;
        maskHi |= (0xFFu << shift);
        __syncthreads();
    }

    const unsigned T = prefix;
    const int needEq = needed;
    const int cgt = PRE_NMS - needEq;

    if (tid == 0) { base_g = 0; base_e = 0; }
    __syncthreads();

    const unsigned lt_mask = (1u << lane) - 1u;
    const float4* bp = reinterpret_cast<const float4*>(g_boxes);

    for (int chunk = 0; chunk < NANCH; chunk += 1024) {
        int j = chunk + tid;
        float s = sc[j];
        unsigned u = score_key(s);
        bool isG = (u > T);
        bool isE = (u == T);
        unsigned gm = __ballot_sync(0xffffffffu, isG);
        unsigned em = __ballot_sync(0xffffffffu, isE);
        if (lane == 0) { warpG[warp] = __popc(gm); warpE[warp] = __popc(em); }
        __syncthreads();
        if (warp == 0) {
            int g = warpG[lane], e = warpE[lane];
            #pragma unroll
            for (int off = 1; off < 32; off <<= 1) {
                int go = __shfl_up_sync(0xffffffffu, g, off);
                int eo = __shfl_up_sync(0xffffffffu, e, off);
                if (lane >= off) { g += go; e += eo; }
            }
            warpG[lane] = g; warpE[lane] = e;
        }
        __syncthreads();
        int wbaseG = (warp == 0) ? 0 : warpG[warp - 1];
        int wbaseE = (warp == 0) ? 0 : warpE[warp - 1];
        int slot = -1;
        if (isG) {
            slot = base_g + wbaseG + __popc(gm & lt_mask);
        } else if (isE) {
            int er = base_e + wbaseE + __popc(em & lt_mask);
            if (er < needEq) slot = cgt + er;
        }
        if (slot >= 0) {
            size_t n = (size_t)b * NANCH + j;
            g_cand_s[b * PRE_NMS + slot] = s;
            g_cand_b[b * PRE_NMS + slot] = bp[n];
        }
        __syncthreads();
        if (tid == 0) { base_g += warpG[31]; base_e += warpE[31]; }
        __syncthreads();
    }
}

// ---------------------------------------------------------------------------
// k4: greedy NMS (argmax ties -> smallest slot == smallest anchor index)
// ---------------------------------------------------------------------------
#define NMS_THREADS 512
__global__ void k_nms(float* __restrict__ out) {
    extern __shared__ float smem[];
    float*  sc = smem;                                    // [6016]
    float4* bx = reinterpret_cast<float4*>(smem + 6016);  // [6000]
    float*  wv = smem + 6016 + PRE_NMS * 4;               // [16]
    int*    wi = reinterpret_cast<int*>(wv + 16);         // [16]
    float*  bestv = reinterpret_cast<float*>(wi + 16);
    int*    besti = reinterpret_cast<int*>(bestv + 1);

    const int b = blockIdx.x;
    const int tid = threadIdx.x;
    const int warp = tid >> 5, lane = tid & 31;

    for (int j = tid; j < PRE_NMS; j += NMS_THREADS) {
        sc[j] = g_cand_s[b * PRE_NMS + j];
        bx[j] = g_cand_b[b * PRE_NMS + j];
    }
    __syncthreads();

    for (int i = 0; i < POST_NMS; ++i) {
        float vm = -INFINITY; int im = 0x7fffffff;
        for (int j = tid; j < PRE_NMS; j += NMS_THREADS) {
            float v = sc[j];
            if (v > vm) { vm = v; im = j; }
        }
        #pragma unroll
        for (int off = 16; off > 0; off >>= 1) {
            float ov = __shfl_down_sync(0xffffffffu, vm, off);
            int   oi = __shfl_down_sync(0xffffffffu, im, off);
            if (ov > vm || (ov == vm && oi < im)) { vm = ov; im = oi; }
        }
        if (lane == 0) { wv[warp] = vm; wi[warp] = im; }
        __syncthreads();
        if (warp == 0) {
            float v = (lane < NMS_THREADS / 32) ? wv[lane] : -INFINITY;
            int   x = (lane < NMS_THREADS / 32) ? wi[lane] : 0x7fffffff;
            #pragma unroll
            for (int off = 8; off > 0; off >>= 1) {
                float ov = __shfl_down_sync(0xffffffffu, v, off);
                int   oi = __shfl_down_sync(0xffffffffu, x, off);
                if (ov > v || (ov == v && oi < x)) { v = ov; x = oi; }
            }
            if (lane == 0) { *bestv = v; *besti = x; }
        }
        __syncthreads();

        float m = *bestv;
        int mi = *besti;
        bool valid = m > NEGF;

        if (!valid) {
            int remain = (POST_NMS - i) * 5;
            float* ro = out + ROIS_OFF + ((size_t)b * POST_NMS + i) * 5;
            for (int k = tid; k < remain; k += NMS_THREADS) ro[k] = 0.f;
            return;
        }

        float4 B = bx[mi];
        if (tid == 0) {
            float* ro = out + ROIS_OFF + ((size_t)b * POST_NMS + i) * 5;
            ro[0] = m; ro[1] = B.x; ro[2] = B.y; ro[3] = B.z; ro[4] = B.w;
        }
        float a1 = __fmul_rn(__fsub_rn(B.z, B.x), __fsub_rn(B.w, B.y));
        for (int j = tid; j < PRE_NMS; j += NMS_THREADS) {
            float v = sc[j];
            if (v == NEGF) continue;
            float4 c = bx[j];
            float x1 = fmaxf(B.x, c.x);
            float y1 = fmaxf(B.y, c.y);
            float x2 = fminf(B.z, c.z);
            float y2 = fminf(B.w, c.w);
            float inter = __fmul_rn(fmaxf(__fsub_rn(x2, x1), 0.f),
                                    fmaxf(__fsub_rn(y2, y1), 0.f));
            float a2 = __fmul_rn(__fsub_rn(c.z, c.x), __fsub_rn(c.w, c.y));
            float denom = __fadd_rn(__fsub_rn(__fadd_rn(a1, a2), inter), 1e-9f);
            float iou = __fdiv_rn(inter, denom);
            if (iou >= 0.7f) sc[j] = NEGF;
        }
        __syncthreads();
    }
}

// ---------------------------------------------------------------------------
// launch
// ---------------------------------------------------------------------------
extern "C" void kernel_launch(void* const* d_in, const int* in_sizes, int n_in,
                              void* d_out, int out_size) {
    (void)in_sizes; (void)n_in; (void)out_size;
    const float* x     = (const float*)d_in[0];
    const float* Wsh   = (const float*)d_in[1];
    const float* bsh   = (const float*)d_in[2];
    const float* Wcls  = (const float*)d_in[3];
    const float* bcls  = (const float*)d_in[4];
    const float* Wreg  = (const float*)d_in[5];
    const float* breg  = (const float*)d_in[6];
    float* out = (float*)d_out;

    k_wt_transform<<<(OC*CIN*9 + 255) / 256, 256>>>(Wsh);
    k_wk_build<<<(CIN*54 + 255) / 256, 256>>>(Wcls, Wreg);

    dim3 cgrid(4, 512);
    k_conv3x3<<<cgrid, 256>>>(x, bsh);

    k_heads<<<NPIX / 256, 256>>>(bcls, breg, out);

    k_select<<<BATCH, 1024>>>();

    int smem_bytes = (6016 + PRE_NMS * 4) * 4 + 16 * 4 + 16 * 4 + 8;
    cudaFuncSetAttribute(k_nms, cudaFuncAttributeMaxDynamicSharedMemorySize, smem_bytes);
    k_nms<<<BATCH, NMS_THREADS, smem_bytes>>>(out);
}